// round 8
// baseline (speedup 1.0000x reference)
#include <cuda_runtime.h>

// OWA pooling: 3x3 / stride 2 / pad(0,1,0,1) over (16,224,224,64) f32 NHWC.
// Per output element: descending-sort the 9 window values, dot with kernel[:,c].
//
// R7: packed-f32x2 sort. Each thread owns one output pixel x 4 channels,
// held as TWO packed u64 lanes (ch pair xy, ch pair zw). Compare-exchange:
//   s  = add.rn.f32x2(A, B)        (1 fma-pipe op for 2 lanes)
//   hi = {max(al,bl), max(ah,bh)}  (2 alu-pipe FMNMX)
//   A  = fma.rn.f32x2(hi, -1, s)   (1 fma-pipe FFMA2)  => lo
// 8 instr per 4-lane comparator vs 12 scalar-hybrid; dot uses FFMA2 (18 vs 36).

namespace {

constexpr int B_DIM = 16;
constexpr int H_IN = 224, W_IN = 224;
constexpr int H_OUT = 112, W_OUT = 112;
constexpr int C4 = 16;                               // 64 channels / 16B chunk
constexpr int TOTAL4 = B_DIM * H_OUT * W_OUT * C4;   // 3,211,264 threads
constexpr int BLOCK = 256;

constexpr unsigned long long NEG1X2 = 0xBF800000BF800000ULL;  // {-1.f, -1.f}

// Packed hybrid compare-exchange on 2 fp32 lanes held in a u64.
// After: A = min (1-ulp-of-sum error), B = max (exact).
__device__ __forceinline__ void cash2(unsigned long long& A, unsigned long long& B) {
  asm("{\n\t"
      ".reg .f32 al, ah, bl, bh, hl, hh;\n\t"
      ".reg .b64 s64;\n\t"
      "add.rn.f32x2 s64, %0, %1;\n\t"
      "mov.b64 {al, ah}, %0;\n\t"
      "mov.b64 {bl, bh}, %1;\n\t"
      "max.f32 hl, al, bl;\n\t"
      "max.f32 hh, ah, bh;\n\t"
      "mov.b64 %1, {hl, hh};\n\t"
      "fma.rn.f32x2 %0, %1, %2, s64;\n\t"
      "}"
      : "+l"(A), "+l"(B)
      : "l"(NEG1X2));
}

__device__ __forceinline__ void fma2(unsigned long long& acc,
                                     unsigned long long v,
                                     unsigned long long w) {
  asm("fma.rn.f32x2 %0, %1, %2, %0;" : "+l"(acc) : "l"(v), "l"(w));
}

// Published optimal 9-element sorting network: 25 comparators, depth 7.
// Two independent packed chains (a = ch xy, b = ch zw) for ILP.
__device__ __forceinline__ void sort9p(unsigned long long (&a)[9],
                                       unsigned long long (&b)[9]) {
#define CE(i,j) cash2(a[i],a[j]); cash2(b[i],b[j]);
  CE(0,3) CE(1,7) CE(2,5) CE(4,8)
  CE(0,7) CE(2,4) CE(3,8) CE(5,6)
  CE(0,2) CE(1,3) CE(4,5) CE(7,8)
  CE(1,4) CE(3,6) CE(5,7)
  CE(0,1) CE(2,4) CE(3,5) CE(6,8)
  CE(2,3) CE(4,5) CE(6,7)
  CE(1,2) CE(3,4) CE(5,6)
#undef CE
}

} // namespace

__global__ __launch_bounds__(BLOCK, 4)
void owa_pool_kernel(const ulonglong2* __restrict__ in2,
                     const ulonglong2* __restrict__ wk2,
                     ulonglong2* __restrict__ out2) {
  int tid = blockIdx.x * BLOCK + threadIdx.x;
  if (tid >= TOTAL4) return;

  int c4  = tid & (C4 - 1);
  int pix = tid >> 4;
  int ow  = pix % W_OUT;
  int t   = pix / W_OUT;
  int oh  = t % H_OUT;
  int b   = t / H_OUT;

  int y0 = oh * 2;
  int x0 = ow * 2;

  unsigned long long vxy[9], vzw[9];
#pragma unroll
  for (int ky = 0; ky < 3; ++ky) {
    int y = y0 + ky;
    bool yok = (y < H_IN);
    int rowbase = (b * H_IN + y) * W_IN;
#pragma unroll
    for (int kx = 0; kx < 3; ++kx) {
      int x = x0 + kx;
      ulonglong2 val = make_ulonglong2(0ULL, 0ULL);
      if (yok && x < W_IN) val = __ldg(&in2[(rowbase + x) * C4 + c4]);
      vxy[ky * 3 + kx] = val.x;
      vzw[ky * 3 + kx] = val.y;
    }
  }

  // Ascending sort; weight k applies to the k-th LARGEST -> pair v[i] with w[8-i].
  sort9p(vxy, vzw);

  unsigned long long axy = 0ULL, azw = 0ULL;  // {0.f,0.f} bit pattern
  const ulonglong2* wkc = wk2 + c4;
#pragma unroll
  for (int k = 0; k < 9; ++k) {
    ulonglong2 w = __ldg(wkc + (8 - k) * C4);
    fma2(axy, vxy[k], w.x);
    fma2(azw, vzw[k], w.y);
  }

  out2[tid] = make_ulonglong2(axy, azw);
}

extern "C" void kernel_launch(void* const* d_in, const int* in_sizes, int n_in,
                              void* d_out, int out_size) {
  const ulonglong2* in2 = (const ulonglong2*)d_in[0];   // (16,224,224,64) f32
  const ulonglong2* wk2 = (const ulonglong2*)d_in[1];   // (9,64) f32
  ulonglong2* out2 = (ulonglong2*)d_out;                // (16,112,112,64) f32

  (void)in_sizes; (void)n_in; (void)out_size;
  int grid = (TOTAL4 + BLOCK - 1) / BLOCK;
  owa_pool_kernel<<<grid, BLOCK>>>(in2, wk2, out2);
}